// round 6
// baseline (speedup 1.0000x reference)
#include <cuda_runtime.h>
#include <cstdint>

static constexpr int   kVocab   = 128000;
static constexpr int   kTopK    = 50;
static constexpr float kTopP    = 0.9f;
static constexpr float kNeg     = -1000000000.0f;
static constexpr int   kThreads = 1024;
static constexpr int   kWCap    = 64;            // per-warp candidate slots
static constexpr int   kCap     = 32 * kWCap;    // 2048 max candidates

// Order-preserving float -> uint32 key (monotone increasing, >0 for any float).
__device__ __forceinline__ unsigned f2key(float f) {
    unsigned b = __float_as_uint(f);
    return (b & 0x80000000u) ? ~b : (b | 0x80000000u);
}
__device__ __forceinline__ float key2f(unsigned k) {
    unsigned b = (k & 0x80000000u) ? (k & 0x7FFFFFFFu) : ~k;
    return __uint_as_float(b);
}
__device__ __forceinline__ unsigned long long shfl_xor64(unsigned long long v, int j) {
    unsigned lo = __shfl_xor_sync(0xffffffffu, (unsigned)v, j);
    unsigned hi = __shfl_xor_sync(0xffffffffu, (unsigned)(v >> 32), j);
    return ((unsigned long long)hi << 32) | lo;
}

// ---------------------------------------------------------------------------
// Kernel 1: pure write stream — NEG-fill the whole output. Perfectly balanced
// grid-stride, no dependencies, no reads.
// ---------------------------------------------------------------------------
__global__ void __launch_bounds__(256)
fill_kernel(float4* __restrict__ out4, int n4) {
    const float4 neg4 = make_float4(kNeg, kNeg, kNeg, kNeg);
    int stride = gridDim.x * blockDim.x;
    int i = blockIdx.x * blockDim.x + threadIdx.x;
#pragma unroll 4
    for (; i < n4; i += stride)
        __stcs(&out4[i], neg4);
}

// ---------------------------------------------------------------------------
// Kernel 2: pure read stream + select + sort + sparse scatter.
// ---------------------------------------------------------------------------
__global__ void __launch_bounds__(kThreads, 2)
select_kernel(const float* __restrict__ in, float* __restrict__ out) {
    __shared__ unsigned long long s_cand[kCap];    // per-warp segments (gaps ok)
    __shared__ unsigned long long s_sorted[kCap];  // compacted + sorted
    __shared__ int   s_wcnt[32];
    __shared__ int   s_woff[32];
    __shared__ float s_wm[32];     // sorted (ascending) warp maxima of samples
    __shared__ float s_ex[kTopK];
    __shared__ float s_T;
    __shared__ int   s_total;
    __shared__ int   s_ovf;
    __shared__ int   s_k;

    const int row  = blockIdx.x;
    const float* rin  = in  + (long long)row * kVocab;
    float*       rout = out + (long long)row * kVocab;
    const int tid  = threadIdx.x;
    const int lane = tid & 31;
    const int wid  = tid >> 5;

    // ---------------- Phase 0: sample-based threshold estimate ----------------
    float sv = __ldcs(&rin[tid * (kVocab / kThreads)]);
#pragma unroll
    for (int o = 16; o > 0; o >>= 1)
        sv = fmaxf(sv, __shfl_xor_sync(0xffffffffu, sv, o));
    if (lane == 0) s_wm[wid] = sv;
    __syncthreads();
    if (wid == 0) {
        float x = s_wm[lane];
#pragma unroll
        for (int k = 2; k <= 32; k <<= 1) {
#pragma unroll
            for (int j = k >> 1; j > 0; j >>= 1) {
                float y     = __shfl_xor_sync(0xffffffffu, x, j);
                bool  up    = ((lane & k) == 0);
                bool  lower = ((lane & j) == 0);
                x = (up == lower) ? fminf(x, y) : fmaxf(x, y);
            }
        }
        s_wm[lane] = x;  // ascending
    }
    if (tid < 32) s_wcnt[tid] = 0;

    int rank = 5;  // 6th-largest warp max; expected exceedance ~750
    __syncthreads();
    if (tid == 0) s_T = s_wm[31 - rank];
    __syncthreads();
    float T = s_T;

    // ---------------- Phase 1: read-only stream, batch-6 loads ----------------
    const float4* rin4 = reinterpret_cast<const float4*>(rin);
    const int n4 = kVocab / 4;

#define PUSH4(v, base)                                                            \
    {                                                                             \
        if (v.x > T) { int p = atomicAdd(&s_wcnt[wid], 1);                        \
            if (p < kWCap) s_cand[wid * kWCap + p] =                              \
                ((unsigned long long)f2key(v.x) << 32) | (unsigned)(base); }      \
        if (v.y > T) { int p = atomicAdd(&s_wcnt[wid], 1);                        \
            if (p < kWCap) s_cand[wid * kWCap + p] =                              \
                ((unsigned long long)f2key(v.y) << 32) | (unsigned)(base + 1); }  \
        if (v.z > T) { int p = atomicAdd(&s_wcnt[wid], 1);                        \
            if (p < kWCap) s_cand[wid * kWCap + p] =                              \
                ((unsigned long long)f2key(v.z) << 32) | (unsigned)(base + 2); }  \
        if (v.w > T) { int p = atomicAdd(&s_wcnt[wid], 1);                        \
            if (p < kWCap) s_cand[wid * kWCap + p] =                              \
                ((unsigned long long)f2key(v.w) << 32) | (unsigned)(base + 3); }  \
    }

    for (int i0 = tid; i0 < n4; i0 += 6 * kThreads) {
        const int i1 = i0 + 1 * kThreads, i2 = i0 + 2 * kThreads,
                  i3 = i0 + 3 * kThreads, i4 = i0 + 4 * kThreads,
                  i5 = i0 + 5 * kThreads;
        const bool h1 = i1 < n4, h2 = i2 < n4, h3 = i3 < n4,
                   h4 = i4 < n4, h5 = i5 < n4;
        float4 a = __ldcs(&rin4[i0]);
        float4 b, c, d, e, f;
        if (h1) b = __ldcs(&rin4[i1]);
        if (h2) c = __ldcs(&rin4[i2]);
        if (h3) d = __ldcs(&rin4[i3]);
        if (h4) e = __ldcs(&rin4[i4]);
        if (h5) f = __ldcs(&rin4[i5]);
        if (fmaxf(fmaxf(a.x, a.y), fmaxf(a.z, a.w)) > T) PUSH4(a, 4 * i0);
        if (h1 && fmaxf(fmaxf(b.x, b.y), fmaxf(b.z, b.w)) > T) PUSH4(b, 4 * i1);
        if (h2 && fmaxf(fmaxf(c.x, c.y), fmaxf(c.z, c.w)) > T) PUSH4(c, 4 * i2);
        if (h3 && fmaxf(fmaxf(d.x, d.y), fmaxf(d.z, d.w)) > T) PUSH4(d, 4 * i3);
        if (h4 && fmaxf(fmaxf(e.x, e.y), fmaxf(e.z, e.w)) > T) PUSH4(e, 4 * i4);
        if (h5 && fmaxf(fmaxf(f.x, f.y), fmaxf(f.z, f.w)) > T) PUSH4(f, 4 * i5);
    }
    __syncthreads();

    // Count + overflow check (warp 0).
    if (wid == 0) {
        int c = s_wcnt[lane];
        int ov = __any_sync(0xffffffffu, c > kWCap) ? 1 : 0;
        int t = c;
#pragma unroll
        for (int o = 16; o > 0; o >>= 1) t += __shfl_xor_sync(0xffffffffu, t, o);
        if (lane == 0) { s_total = t; s_ovf = ov; }
    }
    __syncthreads();
    int total = s_total, ovf = s_ovf;

    // Retry ladder (essentially never taken).
    for (int attempt = 0; attempt < 4 && (total < kTopK || ovf); ++attempt) {
        if (ovf) rank = rank >> 1;                          // raise threshold
        else     rank = (rank < 31) ? (rank * 2 + 1) : 31;  // lower threshold
        __syncthreads();
        if (tid < 32) s_wcnt[tid] = 0;
        if (tid == 0) s_T = s_wm[31 - rank];
        __syncthreads();
        T = s_T;
        for (int i = tid; i < n4; i += kThreads) {
            float4 a = __ldcs(&rin4[i]);
            if (fmaxf(fmaxf(a.x, a.y), fmaxf(a.z, a.w)) > T) PUSH4(a, 4 * i);
        }
        __syncthreads();
        if (wid == 0) {
            int c = s_wcnt[lane];
            int ov = __any_sync(0xffffffffu, c > kWCap) ? 1 : 0;
            int t = c;
#pragma unroll
            for (int o = 16; o > 0; o >>= 1) t += __shfl_xor_sync(0xffffffffu, t, o);
            if (lane == 0) { s_total = t; s_ovf = ov; }
        }
        __syncthreads();
        total = s_total; ovf = s_ovf;
    }
#undef PUSH4

    // ---------------- Phase 1.5: compact per-warp segments into s_sorted ----------------
    if (wid == 0) {
        int c = min(s_wcnt[lane], kWCap);
        int x = c;
#pragma unroll
        for (int o = 1; o < 32; o <<= 1) {
            int y = __shfl_up_sync(0xffffffffu, x, o);
            if (lane >= o) x += y;
        }
        s_woff[lane] = x - c;  // exclusive prefix
    }
    __syncthreads();
    {
        int c   = min(s_wcnt[wid], kWCap);
        int off = s_woff[wid];
        for (int e = lane; e < c; e += 32)
            s_sorted[off + e] = s_cand[wid * kWCap + e];
    }
    __syncthreads();

    // ---------------- Phase 2: bitonic sort (descending) ----------------
    if (total <= kThreads) {
        // Hybrid register bitonic: j>=32 via shared, j<32 via warp shuffles.
        int npad = 64;
        while (npad < total) npad <<= 1;
        const bool act = tid < npad;
        unsigned long long v = 0ull;
        if (act && tid < total) v = s_sorted[tid];

        for (int k = 2; k <= npad; k <<= 1) {
            int j = k >> 1;
            for (; j >= 32; j >>= 1) {
                __syncthreads();
                if (act) s_sorted[tid] = v;
                __syncthreads();
                if (act) {
                    unsigned long long u = s_sorted[tid ^ j];
                    bool takeMax = (((tid & k) == 0) == ((tid & j) == 0));
                    v = takeMax ? (v > u ? v : u) : (v < u ? v : u);
                }
            }
            for (; j > 0; j >>= 1) {
                unsigned long long u = shfl_xor64(v, j);
                bool takeMax = (((tid & k) == 0) == ((tid & j) == 0));
                v = takeMax ? (v > u ? v : u) : (v < u ? v : u);
            }
        }
        __syncthreads();
        if (act) s_sorted[tid] = v;
        __syncthreads();
    } else {
        // Rare fallback (total in (1024, 2048]): shared bitonic over kCap.
        for (int i = total + tid; i < kCap; i += kThreads) s_sorted[i] = 0ull;
        __syncthreads();
        for (int k = 2; k <= kCap; k <<= 1) {
            for (int j = k >> 1; j > 0; j >>= 1) {
#pragma unroll 1
                for (int i = tid; i < kCap; i += kThreads) {
                    int p = i ^ j;
                    if (p > i) {
                        unsigned long long a = s_sorted[i];
                        unsigned long long b = s_sorted[p];
                        bool desc = ((i & k) == 0);
                        if (desc ? (a < b) : (a > b)) { s_sorted[i] = b; s_sorted[p] = a; }
                    }
                }
                __syncthreads();
            }
        }
    }

    // ---------------- Phase 3: softmax cum-prob over top-50 ----------------
    const int lim = (total < kTopK) ? total : kTopK;
    if (wid == 0) {
        float m = key2f((unsigned)(s_sorted[0] >> 32));
#pragma unroll
        for (int j = lane; j < kTopK; j += 32)
            if (j < lim)
                s_ex[j] = expf(key2f((unsigned)(s_sorted[j] >> 32)) - m);
    }
    __syncthreads();
    if (tid == 0) {
        int kk = 0;
        if (lim > 0) {
            float Z = 0.f;
            for (int j = 0; j < lim; ++j) Z += s_ex[j];
            float invZ = 1.0f / Z;
            float cum = 0.f;
            for (int j = 0; j < lim; ++j) {
                if (j > 0 && cum > kTopP) break;
                kk = j + 1;
                cum += s_ex[j] * invZ;
            }
        }
        s_k = kk;
    }
    __syncthreads();

    // ---------------- Phase 4: scatter kept values over the NEG fill ----------------
    if (tid < s_k) {
        unsigned long long c = s_sorted[tid];
        int idx = (int)(c & 0xFFFFFFFFu);
        rout[idx] = key2f((unsigned)(c >> 32));
    }
}

extern "C" void kernel_launch(void* const* d_in, const int* in_sizes, int n_in,
                              void* d_out, int out_size) {
    const float* in = (const float*)d_in[0];
    float* out = (float*)d_out;
    int rows = in_sizes[0] / kVocab;
    int n4 = (rows * kVocab) / 4;
    // Pure write stream first; scatter in select_kernel lands after (same stream).
    fill_kernel<<<2048, 256>>>(reinterpret_cast<float4*>(out), n4);
    select_kernel<<<rows, kThreads>>>(in, out);
}

// round 7
// speedup vs baseline: 1.1226x; 1.1226x over previous
#include <cuda_runtime.h>
#include <cstdint>

static constexpr int   kVocab   = 128000;
static constexpr int   kTopK    = 50;
static constexpr float kTopP    = 0.9f;
static constexpr float kNeg     = -1000000000.0f;
static constexpr int   kThreads = 1024;
static constexpr int   kWCap    = 64;            // per-warp candidate slots
static constexpr int   kCap     = 32 * kWCap;    // 2048 max candidates

static constexpr int   kChunkF  = 4000;              // floats per chunk
static constexpr int   kChunkB  = kChunkF * 4;       // 16000 bytes (16B-mult)
static constexpr int   kNChunks = kVocab / kChunkF;  // 32
static constexpr int   kStages  = 4;

// Dynamic smem layout (byte offsets, all 16B aligned):
static constexpr int OFF_RING  = 0;                        // kStages*kChunkB = 64000
static constexpr int OFF_ALIAS = OFF_RING + kStages * kChunkB;   // 64000: negbuf(16000B) / s_sorted[2048](16384B)
static constexpr int OFF_CAND  = OFF_ALIAS + 16384;        // 80384: s_cand[2048] (16384B)
static constexpr int OFF_MBAR  = OFF_CAND + 16384;         // 96768: 4 x u64
static constexpr int OFF_WCNT  = OFF_MBAR + 32;            // 96800: 32 x int
static constexpr int OFF_WOFF  = OFF_WCNT + 128;           // 32 x int
static constexpr int OFF_WM    = OFF_WOFF + 128;           // 32 x float
static constexpr int OFF_EX    = OFF_WM + 128;             // 50 x float
static constexpr int OFF_SCAL  = OFF_EX + 200;             // T, total, ovf, k
static constexpr int kSmemBytes = OFF_SCAL + 16;           // 97400 -> pad
static constexpr int kSmemAlloc = 97408;

// Order-preserving float -> uint32 key (monotone increasing, >0 for any float).
__device__ __forceinline__ unsigned f2key(float f) {
    unsigned b = __float_as_uint(f);
    return (b & 0x80000000u) ? ~b : (b | 0x80000000u);
}
__device__ __forceinline__ float key2f(unsigned k) {
    unsigned b = (k & 0x80000000u) ? (k & 0x7FFFFFFFu) : ~k;
    return __uint_as_float(b);
}
__device__ __forceinline__ unsigned long long shfl_xor64(unsigned long long v, int j) {
    unsigned lo = __shfl_xor_sync(0xffffffffu, (unsigned)v, j);
    unsigned hi = __shfl_xor_sync(0xffffffffu, (unsigned)(v >> 32), j);
    return ((unsigned long long)hi << 32) | lo;
}

// ---- async-proxy helpers -------------------------------------------------
__device__ __forceinline__ void mbar_init(unsigned mbar, unsigned cnt) {
    asm volatile("mbarrier.init.shared::cta.b64 [%0], %1;" :: "r"(mbar), "r"(cnt) : "memory");
}
__device__ __forceinline__ void mbar_expect_tx(unsigned mbar, unsigned bytes) {
    asm volatile("mbarrier.arrive.expect_tx.shared::cta.b64 _, [%0], %1;"
                 :: "r"(mbar), "r"(bytes) : "memory");
}
__device__ __forceinline__ void mbar_wait_parity(unsigned mbar, unsigned parity) {
    asm volatile(
        "{\n\t.reg .pred P;\n\t"
        "WL_%=:\n\t"
        "mbarrier.try_wait.parity.acquire.cta.shared::cta.b64 P, [%0], %1, 0x989680;\n\t"
        "@P bra.uni WD_%=;\n\t"
        "bra.uni WL_%=;\n\t"
        "WD_%=:\n\t}"
        :: "r"(mbar), "r"(parity) : "memory");
}
__device__ __forceinline__ void bulk_g2s(unsigned sdst, const void* gsrc, unsigned bytes, unsigned mbar) {
    asm volatile(
        "cp.async.bulk.shared::cta.global.mbarrier::complete_tx::bytes [%0], [%1], %2, [%3];"
        :: "r"(sdst), "l"(gsrc), "r"(bytes), "r"(mbar) : "memory");
}
__device__ __forceinline__ void bulk_s2g(void* gdst, unsigned ssrc, unsigned bytes) {
    asm volatile("cp.async.bulk.global.shared::cta.bulk_group [%0], [%1], %2;"
                 :: "l"(gdst), "r"(ssrc), "r"(bytes) : "memory");
    asm volatile("cp.async.bulk.commit_group;" ::: "memory");
}
__device__ __forceinline__ void bulk_wait_all() {
    asm volatile("cp.async.bulk.wait_group 0;" ::: "memory");
}
__device__ __forceinline__ void fence_async_shared() {
    asm volatile("fence.proxy.async.shared::cta;" ::: "memory");
}

__global__ void __launch_bounds__(kThreads, 2)
topk_topp_kernel(const float* __restrict__ in, float* __restrict__ out) {
    extern __shared__ __align__(16) char smem[];
    float*              ring     = reinterpret_cast<float*>(smem + OFF_RING);
    float*              negbuf   = reinterpret_cast<float*>(smem + OFF_ALIAS);   // phase 1
    unsigned long long* s_sorted = reinterpret_cast<unsigned long long*>(smem + OFF_ALIAS); // phase >=2
    unsigned long long* s_cand   = reinterpret_cast<unsigned long long*>(smem + OFF_CAND);
    int*   s_wcnt = reinterpret_cast<int*>(smem + OFF_WCNT);
    int*   s_woff = reinterpret_cast<int*>(smem + OFF_WOFF);
    float* s_wm   = reinterpret_cast<float*>(smem + OFF_WM);
    float* s_ex   = reinterpret_cast<float*>(smem + OFF_EX);
    float* s_T    = reinterpret_cast<float*>(smem + OFF_SCAL);
    int*   s_total= reinterpret_cast<int*>(smem + OFF_SCAL + 4);
    int*   s_ovf  = reinterpret_cast<int*>(smem + OFF_SCAL + 8);
    int*   s_k    = reinterpret_cast<int*>(smem + OFF_SCAL + 12);

    const unsigned smem_base = (unsigned)__cvta_generic_to_shared(smem);
    const unsigned ring_s    = smem_base + OFF_RING;
    const unsigned negbuf_s  = smem_base + OFF_ALIAS;
    const unsigned mbar_s    = smem_base + OFF_MBAR;

    const int row  = blockIdx.x;
    const float* rin  = in  + (long long)row * kVocab;
    float*       rout = out + (long long)row * kVocab;
    const int tid  = threadIdx.x;
    const int lane = tid & 31;
    const int wid  = tid >> 5;

    // ---------------- Phase 0: sample-based threshold estimate ----------------
    float sv = __ldg(&rin[tid * (kVocab / kThreads)]);
#pragma unroll
    for (int o = 16; o > 0; o >>= 1)
        sv = fmaxf(sv, __shfl_xor_sync(0xffffffffu, sv, o));
    if (lane == 0) s_wm[wid] = sv;

    // NEG buffer fill (1000 float4) + barrier inits, concurrent with phase 0.
    if (tid < kChunkF / 4) {
        float4* nb4 = reinterpret_cast<float4*>(negbuf);
        nb4[tid] = make_float4(kNeg, kNeg, kNeg, kNeg);
    }
    if (tid < 32) s_wcnt[tid] = 0;
    if (tid == 0) {
#pragma unroll
        for (int s = 0; s < kStages; ++s) mbar_init(mbar_s + 8 * s, 1);
    }
    fence_async_shared();
    __syncthreads();

    if (wid == 0) {
        float x = s_wm[lane];
#pragma unroll
        for (int k = 2; k <= 32; k <<= 1) {
#pragma unroll
            for (int j = k >> 1; j > 0; j >>= 1) {
                float y     = __shfl_xor_sync(0xffffffffu, x, j);
                bool  up    = ((lane & k) == 0);
                bool  lower = ((lane & j) == 0);
                x = (up == lower) ? fminf(x, y) : fmaxf(x, y);
            }
        }
        s_wm[lane] = x;  // ascending
    }
    int rank = 5;  // 6th-largest warp max; expected exceedance ~750
    __syncthreads();
    if (tid == 0) *s_T = s_wm[31 - rank];
    __syncthreads();
    float T = *s_T;

    // ---------------- Phase 1: bulk-copy pipeline: read chunks, NEG-store chunks ----------------
#define PUSH4(v, base)                                                            \
    {                                                                             \
        if (v.x > T) { int p = atomicAdd(&s_wcnt[wid], 1);                        \
            if (p < kWCap) s_cand[wid * kWCap + p] =                              \
                ((unsigned long long)f2key(v.x) << 32) | (unsigned)(base); }      \
        if (v.y > T) { int p = atomicAdd(&s_wcnt[wid], 1);                        \
            if (p < kWCap) s_cand[wid * kWCap + p] =                              \
                ((unsigned long long)f2key(v.y) << 32) | (unsigned)(base + 1); }  \
        if (v.z > T) { int p = atomicAdd(&s_wcnt[wid], 1);                        \
            if (p < kWCap) s_cand[wid * kWCap + p] =                              \
                ((unsigned long long)f2key(v.z) << 32) | (unsigned)(base + 2); }  \
        if (v.w > T) { int p = atomicAdd(&s_wcnt[wid], 1);                        \
            if (p < kWCap) s_cand[wid * kWCap + p] =                              \
                ((unsigned long long)f2key(v.w) << 32) | (unsigned)(base + 3); }  \
    }

    // Prologue: issue first kStages chunk loads.
    if (tid == 0) {
#pragma unroll
        for (int s = 0; s < kStages; ++s) {
            mbar_expect_tx(mbar_s + 8 * s, kChunkB);
            bulk_g2s(ring_s + s * kChunkB, rin + s * kChunkF, kChunkB, mbar_s + 8 * s);
        }
    }

    for (int c = 0; c < kNChunks; ++c) {
        const int slot = c & (kStages - 1);
        const unsigned parity = (c >> 2) & 1;
        mbar_wait_parity(mbar_s + 8 * slot, parity);

        // Scan chunk: one float4 per thread (tid < 1000).
        if (tid < kChunkF / 4) {
            const float4* ch4 = reinterpret_cast<const float4*>(ring + slot * kChunkF);
            float4 a = ch4[tid];
            if (fmaxf(fmaxf(a.x, a.y), fmaxf(a.z, a.w)) > T)
                PUSH4(a, c * kChunkF + tid * 4);
        }
        // NEG-fill this output chunk via async bulk store (fire-and-forget).
        if (tid == 0)
            bulk_s2g(rout + c * kChunkF, negbuf_s, kChunkB);
        __syncthreads();  // all threads done reading slot
        if (tid == 0 && c + kStages < kNChunks) {
            mbar_expect_tx(mbar_s + 8 * slot, kChunkB);
            bulk_g2s(ring_s + slot * kChunkB, rin + (c + kStages) * kChunkF,
                     kChunkB, mbar_s + 8 * slot);
        }
    }

    // Count + overflow check (warp 0).
    if (wid == 0) {
        int c = s_wcnt[lane];
        int ov = __any_sync(0xffffffffu, c > kWCap) ? 1 : 0;
        int t = c;
#pragma unroll
        for (int o = 16; o > 0; o >>= 1) t += __shfl_xor_sync(0xffffffffu, t, o);
        if (lane == 0) { *s_total = t; *s_ovf = ov; }
    }
    __syncthreads();
    int total = *s_total, ovf = *s_ovf;

    // Retry ladder (essentially never taken) — plain LDG re-stream.
    for (int attempt = 0; attempt < 4 && (total < kTopK || ovf); ++attempt) {
        if (ovf) rank = rank >> 1;                          // raise threshold
        else     rank = (rank < 31) ? (rank * 2 + 1) : 31;  // lower threshold
        __syncthreads();
        if (tid < 32) s_wcnt[tid] = 0;
        if (tid == 0) *s_T = s_wm[31 - rank];
        __syncthreads();
        T = *s_T;
        const float4* rin4 = reinterpret_cast<const float4*>(rin);
        for (int i = tid; i < kVocab / 4; i += kThreads) {
            float4 a = __ldg(&rin4[i]);
            if (fmaxf(fmaxf(a.x, a.y), fmaxf(a.z, a.w)) > T) PUSH4(a, 4 * i);
        }
        __syncthreads();
        if (wid == 0) {
            int c = s_wcnt[lane];
            int ov = __any_sync(0xffffffffu, c > kWCap) ? 1 : 0;
            int t = c;
#pragma unroll
            for (int o = 16; o > 0; o >>= 1) t += __shfl_xor_sync(0xffffffffu, t, o);
            if (lane == 0) { *s_total = t; *s_ovf = ov; }
        }
        __syncthreads();
        total = *s_total; ovf = *s_ovf;
    }
#undef PUSH4

    // Drain all bulk NEG stores (negbuf free; s_sorted alias becomes usable).
    if (tid == 0) bulk_wait_all();
    __syncthreads();

    // ---------------- Phase 1.5: compact per-warp segments into s_sorted ----------------
    if (wid == 0) {
        int c = min(s_wcnt[lane], kWCap);
        int x = c;
#pragma unroll
        for (int o = 1; o < 32; o <<= 1) {
            int y = __shfl_up_sync(0xffffffffu, x, o);
            if (lane >= o) x += y;
        }
        s_woff[lane] = x - c;  // exclusive prefix
    }
    __syncthreads();
    {
        int c   = min(s_wcnt[wid], kWCap);
        int off = s_woff[wid];
        for (int e = lane; e < c; e += 32)
            s_sorted[off + e] = s_cand[wid * kWCap + e];
    }
    __syncthreads();

    // ---------------- Phase 2: bitonic sort (descending) ----------------
    if (total <= kThreads) {
        int npad = 64;
        while (npad < total) npad <<= 1;
        const bool act = tid < npad;
        unsigned long long v = 0ull;
        if (act && tid < total) v = s_sorted[tid];

        for (int k = 2; k <= npad; k <<= 1) {
            int j = k >> 1;
            for (; j >= 32; j >>= 1) {
                __syncthreads();
                if (act) s_sorted[tid] = v;
                __syncthreads();
                if (act) {
                    unsigned long long u = s_sorted[tid ^ j];
                    bool takeMax = (((tid & k) == 0) == ((tid & j) == 0));
                    v = takeMax ? (v > u ? v : u) : (v < u ? v : u);
                }
            }
            for (; j > 0; j >>= 1) {
                unsigned long long u = shfl_xor64(v, j);
                bool takeMax = (((tid & k) == 0) == ((tid & j) == 0));
                v = takeMax ? (v > u ? v : u) : (v < u ? v : u);
            }
        }
        __syncthreads();
        if (act) s_sorted[tid] = v;
        __syncthreads();
    } else {
        // Rare fallback (total in (1024, 2048]): shared bitonic over kCap.
        for (int i = total + tid; i < kCap; i += kThreads) s_sorted[i] = 0ull;
        __syncthreads();
        for (int k = 2; k <= kCap; k <<= 1) {
            for (int j = k >> 1; j > 0; j >>= 1) {
#pragma unroll 1
                for (int i = tid; i < kCap; i += kThreads) {
                    int p = i ^ j;
                    if (p > i) {
                        unsigned long long a = s_sorted[i];
                        unsigned long long b = s_sorted[p];
                        bool desc = ((i & k) == 0);
                        if (desc ? (a < b) : (a > b)) { s_sorted[i] = b; s_sorted[p] = a; }
                    }
                }
                __syncthreads();
            }
        }
    }

    // ---------------- Phase 3: softmax cum-prob over top-50 ----------------
    const int lim = (total < kTopK) ? total : kTopK;
    if (wid == 0) {
        float m = key2f((unsigned)(s_sorted[0] >> 32));
#pragma unroll
        for (int j = lane; j < kTopK; j += 32)
            if (j < lim)
                s_ex[j] = expf(key2f((unsigned)(s_sorted[j] >> 32)) - m);
    }
    __syncthreads();
    if (tid == 0) {
        int kk = 0;
        if (lim > 0) {
            float Z = 0.f;
            for (int j = 0; j < lim; ++j) Z += s_ex[j];
            float invZ = 1.0f / Z;
            float cum = 0.f;
            for (int j = 0; j < lim; ++j) {
                if (j > 0 && cum > kTopP) break;
                kk = j + 1;
                cum += s_ex[j] * invZ;
            }
        }
        *s_k = kk;
    }
    __syncthreads();

    // ---------------- Phase 4: scatter kept values over the NEG fill ----------------
    if (tid < *s_k) {
        unsigned long long c = s_sorted[tid];
        int idx = (int)(c & 0xFFFFFFFFu);
        rout[idx] = key2f((unsigned)(c >> 32));
    }
}

extern "C" void kernel_launch(void* const* d_in, const int* in_sizes, int n_in,
                              void* d_out, int out_size) {
    const float* in = (const float*)d_in[0];
    float* out = (float*)d_out;
    int rows = in_sizes[0] / kVocab;
    cudaFuncSetAttribute(topk_topp_kernel,
                         cudaFuncAttributeMaxDynamicSharedMemorySize, kSmemAlloc);
    topk_topp_kernel<<<rows, kThreads, kSmemAlloc>>>(in, out);
}